// round 12
// baseline (speedup 1.0000x reference)
#include <cuda_runtime.h>
#include <cuda_bf16.h>
#include <cstdint>
#include <math.h>

#define BATCH 32
#define SEQ   1024
#define DIM   1024
#define BSTRIDE ((size_t)SEQ * DIM)

// ---------------- scratch ---------------------------------------------------
__device__ float g_E  [(size_t)BATCH * SEQ * SEQ];   // E, then rowsoftmax(E) in-place
__device__ float g_WcT[(size_t)BATCH * SEQ * SEQ];   // colsoftmax(E)^T
__device__ float g_rowmax[BATCH * SEQ];
__device__ float g_rowinv[BATCH * SEQ];
__device__ float g_colmax[BATCH * SEQ];
__device__ float g_colinv[BATCH * SEQ];

// ---------------- helpers ---------------------------------------------------
__device__ __forceinline__ float cvt_tf32(float x) {
    float r;
    asm("cvt.rna.tf32.f32 %0, %1;" : "=f"(r) : "f"(x));
    return r;
}
// tf32 m16n8k8
__device__ __forceinline__ void mma8(float* c, const uint4 a, const uint2 b) {
    asm volatile(
        "mma.sync.aligned.m16n8k8.row.col.f32.tf32.tf32.f32 "
        "{%0,%1,%2,%3}, {%4,%5,%6,%7}, {%8,%9}, {%0,%1,%2,%3};"
        : "+f"(c[0]), "+f"(c[1]), "+f"(c[2]), "+f"(c[3])
        : "r"(a.x), "r"(a.y), "r"(a.z), "r"(a.w), "r"(b.x), "r"(b.y));
}
// bf16 m16n8k16
__device__ __forceinline__ void mma16(float* c, const uint4 a, const uint2 b) {
    asm volatile(
        "mma.sync.aligned.m16n8k16.row.col.f32.bf16.bf16.f32 "
        "{%0,%1,%2,%3}, {%4,%5,%6,%7}, {%8,%9}, {%0,%1,%2,%3};"
        : "+f"(c[0]), "+f"(c[1]), "+f"(c[2]), "+f"(c[3])
        : "r"(a.x), "r"(a.y), "r"(a.z), "r"(a.w), "r"(b.x), "r"(b.y));
}
// Dekker bf16 split of two floats -> packed bf16x2 hi / lo (low half = first value)
__device__ __forceinline__ void split2(float x0, float x1, uint32_t& hi, uint32_t& lo) {
    __nv_bfloat16 h0 = __float2bfloat16(x0), h1 = __float2bfloat16(x1);
    __nv_bfloat16 l0 = __float2bfloat16(x0 - __bfloat162float(h0));
    __nv_bfloat16 l1 = __float2bfloat16(x1 - __bfloat162float(h1));
    hi = ((uint32_t)__bfloat16_as_ushort(h1) << 16) | __bfloat16_as_ushort(h0);
    lo = ((uint32_t)__bfloat16_as_ushort(l1) << 16) | __bfloat16_as_ushort(l0);
}

// ============================================================================
// GEMM1: E = P @ H^T  (bf16 hi/lo split, 3-term, m16n8k16)
// 128x128 tile, BK=32 (= 2 k16 steps), 8 warps each 64x32.
// Fragment-gather smem: A-slot(prrow, ks*4+cq) = uint4 [(r,kp0),(r+8,kp0),(r,kp0+4),(r+8,kp0+4)]
// strides: A plane 12 slots/prrow, B plane 12 slots/col (bank-verified).
// ============================================================================
#define G1_APL 3072          // uints per A plane (64*12*4)
#define G1_BPL 3072          // uints per B plane (128*12*2)
#define G1_STG 12288         // uints per stage: Ah, Al, Bh, Bl
#define G1_SMEM (2 * G1_STG * 4)

__device__ __forceinline__ int a1addr(int row, int kp) {
    return (((row >> 4) * 8 + (row & 7)) * 12 + (kp >> 3) * 4 + (kp & 3)) * 4
           + ((row >> 3) & 1) + 2 * ((kp >> 2) & 1);
}
__device__ __forceinline__ int b1addr(int col, int kp) {
    return (col * 12 + (kp >> 3) * 4 + (kp & 3)) * 2 + ((kp >> 2) & 1);
}

__global__ void __launch_bounds__(256, 2)
gemm1_kernel(const float* __restrict__ P, const float* __restrict__ H)
{
    extern __shared__ uint32_t smu[];
    const int tid = threadIdx.x, lane = tid & 31, wid = tid >> 5;
    const int bz = blockIdx.z;
    const int m0 = blockIdx.y * 128, n0 = blockIdx.x * 128;
    const float* Ab = P + (size_t)bz * BSTRIDE + (size_t)m0 * DIM;
    const float* Bb = H + (size_t)bz * BSTRIDE + (size_t)n0 * DIM;
    const int wm = wid & 1, wn = wid >> 1;
    const int r = lane >> 2, cq = lane & 3;

    float acc[4][4][4] = {};

    auto stage = [&](int kt, uint32_t* buf) {
        #pragma unroll
        for (int j = 0; j < 4; j++) {
            const int i = tid + j * 256, row = i >> 3, qc = i & 7;
            float4 va = *(const float4*)(Ab + (size_t)row * DIM + kt * 32 + qc * 4);
            float4 vb = *(const float4*)(Bb + (size_t)row * DIM + kt * 32 + qc * 4);
            uint32_t h, l; int ad;
            split2(va.x, va.y, h, l); ad = a1addr(row, 2 * qc);     buf[ad] = h; buf[G1_APL + ad] = l;
            split2(va.z, va.w, h, l); ad = a1addr(row, 2 * qc + 1); buf[ad] = h; buf[G1_APL + ad] = l;
            split2(vb.x, vb.y, h, l); ad = b1addr(row, 2 * qc);     buf[2*G1_APL + ad] = h; buf[2*G1_APL + G1_BPL + ad] = l;
            split2(vb.z, vb.w, h, l); ad = b1addr(row, 2 * qc + 1); buf[2*G1_APL + ad] = h; buf[2*G1_APL + G1_BPL + ad] = l;
        }
    };

    auto comp = [&](const uint32_t* buf) {
        const uint32_t* sBh = buf + 2 * G1_APL;
        const uint32_t* sBl = sBh + G1_BPL;
        #pragma unroll
        for (int ks = 0; ks < 2; ks++) {
            const int aoff = ks * 4 + cq;
            uint4 Ah[4], Al[4];
            #pragma unroll
            for (int ma = 0; ma < 4; ma++) {
                const int ps = (((wm * 4 + ma) * 8 + r) * 12 + aoff) * 4;
                Ah[ma] = *(const uint4*)(buf + ps);
                Al[ma] = *(const uint4*)(buf + G1_APL + ps);
            }
            #pragma unroll
            for (int na = 0; na < 4; na++) {
                const int bs = ((wn * 32 + na * 8 + r) * 12 + aoff) * 2;
                uint2 bh = *(const uint2*)(sBh + bs);
                uint2 bl = *(const uint2*)(sBl + bs);
                #pragma unroll
                for (int ma = 0; ma < 4; ma++) {
                    mma16(acc[ma][na], Ah[ma], bh);
                    mma16(acc[ma][na], Al[ma], bh);
                    mma16(acc[ma][na], Ah[ma], bl);
                }
            }
        }
    };

    stage(0, smu);
    __syncthreads();
    for (int kt = 0; kt < 32; kt++) {
        comp(smu + (kt & 1) * G1_STG);
        if (kt < 31) {
            stage(kt + 1, smu + ((kt + 1) & 1) * G1_STG);
            __syncthreads();
        }
    }

    float* Cb = g_E + (size_t)bz * SEQ * SEQ;
    #pragma unroll
    for (int ma = 0; ma < 4; ma++) {
        const int row = m0 + wm * 64 + ma * 16 + r;
        #pragma unroll
        for (int na = 0; na < 4; na++) {
            const int col = n0 + wn * 32 + na * 8 + 2 * cq;
            *(float2*)&Cb[(size_t)row * SEQ + col]       = make_float2(acc[ma][na][0], acc[ma][na][1]);
            *(float2*)&Cb[(size_t)(row + 8) * SEQ + col] = make_float2(acc[ma][na][2], acc[ma][na][3]);
        }
    }
}

// ============================================================================
// GEMM2/3 merged: plain tf32 m16n8k8.
//   z<32:  C=outp, A=g_E (row-weighted, NT), B=H (NN)
//   z>=32: C=outh, A=g_WcT (NT),             B=P (NN)
// A plane stride 20 slots/prrow (uint4); B plane stride 21 slots/col (uint2).
// ============================================================================
#define G2_APL 5120          // 64*20*4 uints
#define G2_BPL 5376          // 128*21*2 uints
#define G2_STG 10496
#define G2_SMEM (2 * G2_STG * 4)

__device__ __forceinline__ int a2addr(int row, int c) {
    return (((row >> 4) * 8 + (row & 7)) * 20 + (c >> 3) * 4 + (c & 3)) * 4
           + ((row >> 3) & 1) + 2 * ((c >> 2) & 1);
}
__device__ __forceinline__ int b2addr(int n, int k) {
    return (n * 21 + (k >> 3) * 4 + (k & 3)) * 2 + ((k >> 2) & 1);
}

__global__ void __launch_bounds__(256, 2)
gemm23_kernel(const float* __restrict__ H, const float* __restrict__ P,
              float* __restrict__ outp, float* __restrict__ outh)
{
    extern __shared__ uint32_t smu[];
    const int tid = threadIdx.x, lane = tid & 31, wid = tid >> 5;
    const int z = blockIdx.z;
    const int bz = z & 31, sel = z >> 5;
    const int m0 = blockIdx.y * 128, n0 = blockIdx.x * 128;

    const float* As = (sel ? (const float*)g_WcT : (const float*)g_E)
                      + (size_t)bz * SEQ * SEQ + (size_t)m0 * SEQ;
    const float* Bs = (sel ? P : H) + (size_t)bz * BSTRIDE + n0;
    float* Cb = (sel ? outh : outp) + (size_t)bz * BSTRIDE;

    const int wm = wid & 1, wn = wid >> 1;
    const int r = lane >> 2, cq = lane & 3;

    float acc[4][4][4] = {};

    auto stage = [&](int kt, uint32_t* buf) {
        #pragma unroll
        for (int j = 0; j < 4; j++) {            // A: NT, float4 along k
            const int i = tid + j * 256, row = i >> 3, qc = i & 7;
            float4 va = *(const float4*)(As + (size_t)row * SEQ + kt * 32 + qc * 4);
            buf[a2addr(row, qc * 4 + 0)] = __float_as_uint(cvt_tf32(va.x));
            buf[a2addr(row, qc * 4 + 1)] = __float_as_uint(cvt_tf32(va.y));
            buf[a2addr(row, qc * 4 + 2)] = __float_as_uint(cvt_tf32(va.z));
            buf[a2addr(row, qc * 4 + 3)] = __float_as_uint(cvt_tf32(va.w));
        }
        uint32_t* bbuf = buf + G2_APL;
        #pragma unroll
        for (int jj = 0; jj < 16; jj++) {        // B: NN, scalar loads (bank-friendly scatter)
            const int idx = tid + jj * 256;
            const int krow = idx >> 7, n = idx & 127;
            float v = Bs[(size_t)(kt * 32 + krow) * DIM + n];
            bbuf[b2addr(n, krow)] = __float_as_uint(cvt_tf32(v));
        }
    };

    auto comp = [&](const uint32_t* buf) {
        const uint32_t* sB = buf + G2_APL;
        #pragma unroll
        for (int ks = 0; ks < 4; ks++) {
            const int aoff = ks * 4 + cq;
            uint4 Af[4];
            #pragma unroll
            for (int ma = 0; ma < 4; ma++)
                Af[ma] = *(const uint4*)(buf + (((wm * 4 + ma) * 8 + r) * 20 + aoff) * 4);
            #pragma unroll
            for (int na = 0; na < 4; na++) {
                uint2 bf = *(const uint2*)(sB + ((wn * 32 + na * 8 + r) * 21 + aoff) * 2);
                #pragma unroll
                for (int ma = 0; ma < 4; ma++) mma8(acc[ma][na], Af[ma], bf);
            }
        }
    };

    stage(0, smu);
    __syncthreads();
    for (int kt = 0; kt < 32; kt++) {
        comp(smu + (kt & 1) * G2_STG);
        if (kt < 31) {
            stage(kt + 1, smu + ((kt + 1) & 1) * G2_STG);
            __syncthreads();
        }
    }

    #pragma unroll
    for (int ma = 0; ma < 4; ma++) {
        const int row = m0 + wm * 64 + ma * 16 + r;
        #pragma unroll
        for (int na = 0; na < 4; na++) {
            const int col = n0 + wn * 32 + na * 8 + 2 * cq;
            *(float2*)&Cb[(size_t)row * DIM + col]       = make_float2(acc[ma][na][0], acc[ma][na][1]);
            *(float2*)&Cb[(size_t)(row + 8) * DIM + col] = make_float2(acc[ma][na][2], acc[ma][na][3]);
        }
    }
}

// ---------------- softmax stats ---------------------------------------------
__global__ __launch_bounds__(256)
void row_stats_kernel() {
    const int b = blockIdx.y;
    const int warp = threadIdx.x >> 5, lane = threadIdx.x & 31;
    const int row = blockIdx.x * 8 + warp;
    const float* Erow = g_E + (size_t)b * SEQ * SEQ + (size_t)row * SEQ;
    float m = -INFINITY, s = 0.f;
    #pragma unroll 4
    for (int j = lane; j < SEQ; j += 32) {
        float v = Erow[j];
        if (v > m) { s = s * __expf(m - v) + 1.f; m = v; }
        else       { s += __expf(v - m); }
    }
    #pragma unroll
    for (int off = 16; off; off >>= 1) {
        float om = __shfl_down_sync(0xffffffffu, m, off);
        float os = __shfl_down_sync(0xffffffffu, s, off);
        float nm = fmaxf(m, om);
        s = s * __expf(m - nm) + os * __expf(om - nm);
        m = nm;
    }
    if (lane == 0) { g_rowmax[b * SEQ + row] = m; g_rowinv[b * SEQ + row] = 1.f / s; }
}

__global__ __launch_bounds__(256)
void col_stats_kernel() {
    const int b = blockIdx.y;
    const int j = blockIdx.x * 256 + threadIdx.x;
    const float* Eb = g_E + (size_t)b * SEQ * SEQ;
    float m = -INFINITY, s = 0.f;
    #pragma unroll 4
    for (int i = 0; i < SEQ; i++) {
        float v = Eb[(size_t)i * SEQ + j];
        if (v > m) { s = s * __expf(m - v) + 1.f; m = v; }
        else       { s += __expf(v - m); }
    }
    g_colmax[b * SEQ + j] = m;
    g_colinv[b * SEQ + j] = 1.f / s;
}

// Fused: WcT[j][i] = colsoftmax weight; E[i][j] <- rowsoftmax weight (in place).
// One read of E instead of two.
__global__ __launch_bounds__(256)
void wctwr_kernel() {
    __shared__ float t[32][33];
    __shared__ float rm_s[32], ri_s[32];
    const int b = blockIdx.z;
    float* Eb = g_E + (size_t)b * SEQ * SEQ;
    float* Wb = g_WcT + (size_t)b * SEQ * SEQ;
    const int j = blockIdx.x * 32 + threadIdx.x;
    const int i0 = blockIdx.y * 32;
    const float cm = g_colmax[b * SEQ + j];
    const float ci = g_colinv[b * SEQ + j];
    if (threadIdx.y == 0) {
        rm_s[threadIdx.x] = g_rowmax[b * SEQ + i0 + threadIdx.x];
        ri_s[threadIdx.x] = g_rowinv[b * SEQ + i0 + threadIdx.x];
    }
    __syncthreads();
    #pragma unroll
    for (int rr = threadIdx.y; rr < 32; rr += 8) {
        const size_t idx = (size_t)(i0 + rr) * SEQ + j;
        float e = Eb[idx];
        Eb[idx] = __expf(e - rm_s[rr]) * ri_s[rr];
        t[rr][threadIdx.x] = __expf(e - cm) * ci;
    }
    __syncthreads();
    const int i2 = blockIdx.y * 32 + threadIdx.x;
    const int j2 = blockIdx.x * 32;
    #pragma unroll
    for (int rr = threadIdx.y; rr < 32; rr += 8)
        Wb[(size_t)(j2 + rr) * SEQ + i2] = t[threadIdx.x][rr];
}

// ---------------------------------------------------------------------------
extern "C" void kernel_launch(void* const* d_in, const int* in_sizes, int n_in,
                              void* d_out, int out_size) {
    const float* P = (const float*)d_in[0];
    const float* H = (const float*)d_in[1];
    float* outp = (float*)d_out;
    float* outh = (float*)d_out + (size_t)BATCH * SEQ * DIM;

    cudaFuncSetAttribute(gemm1_kernel,  cudaFuncAttributeMaxDynamicSharedMemorySize, G1_SMEM);
    cudaFuncSetAttribute(gemm23_kernel, cudaFuncAttributeMaxDynamicSharedMemorySize, G2_SMEM);

    gemm1_kernel<<<dim3(8, 8, BATCH), 256, G1_SMEM>>>(P, H);
    row_stats_kernel<<<dim3(SEQ / 8, BATCH), 256>>>();
    col_stats_kernel<<<dim3(SEQ / 256, BATCH), 256>>>();
    wctwr_kernel<<<dim3(32, 32, BATCH), dim3(32, 8)>>>();
    gemm23_kernel<<<dim3(8, 8, 2 * BATCH), 256, G2_SMEM>>>(H, P, outp, outh);
}